// round 15
// baseline (speedup 1.0000x reference)
#include <cuda_runtime.h>
#include <cuda_fp16.h>
#include <math.h>
#include <stdint.h>

// Problem constants
#define B_ 8
#define T_ 2048
#define D_ 1024
#define H_ 4
#define DK_ 256
#define DV_ 256
#define NH_ 2
#define KC_ 4
#define I_ 2816
#define EPS_ 1e-6f

#define MT_ (B_*T_)          // 16384 rows

// ---------------- scratch (device globals; no allocation allowed) ----------------
__device__ float g_es[B_*D_];
__device__ float g_ge[B_*D_];
__device__ float g_gx[MT_*D_];
__device__ float g_xf[MT_*D_];
__device__ float g_h [MT_*D_];
__device__ float g_qlin[MT_*D_];
__device__ float g_klin[MT_*2048];
__device__ float g_vlin[MT_*2048];
__device__ float g_qn[MT_*D_];          // [B,H,T,DK]
__device__ float g_kn[MT_*2048];        // [B,NH*H,T,DK]
__device__ float g_vn[MT_*2048];        // [B,NH*H,T,DV]
__device__ float g_beta[B_*NH_*H_*T_];
__device__ float g_eg[B_*H_*T_];
__device__ float g_o [MT_*D_];          // [B,T,H,DV]
__device__ float g_x2[MT_*D_];
__device__ float g_gl[MT_*I_];

// fp16 hi/lo split scratch (activations)
__device__ __half g_xh[MT_*D_],  g_xl[MT_*D_];
__device__ __half g_hh[MT_*D_],  g_hl[MT_*D_];
__device__ __half g_onh[MT_*D_], g_onl[MT_*D_];
__device__ __half g_h2h[MT_*D_], g_h2l[MT_*D_];
__device__ __half g_mh[MT_*I_],  g_ml[MT_*I_];
// fp16 weights (hi only used by GEMM)
__device__ __half g_wsgh[D_*D_];
__device__ __half g_wqh[D_*D_];
__device__ __half g_wkh[2048*D_];
__device__ __half g_wvh[2048*D_];
__device__ __half g_woh[D_*D_];
__device__ __half g_wgh[I_*D_];
__device__ __half g_wuh[I_*D_];
__device__ __half g_wdh[D_*I_];

// ---------------- helpers ----------------
__device__ __forceinline__ float sigmoidf_(float x){ return 1.f/(1.f+expf(-x)); }
__device__ __forceinline__ float softplusf_(float x){ return x>20.f? x : log1pf(expf(x)); }

__device__ __forceinline__ float blockReduce256(float v){
    __shared__ float sh[8];
    #pragma unroll
    for(int o=16;o;o>>=1) v += __shfl_xor_sync(0xffffffffu, v, o);
    if((threadIdx.x&31)==0) sh[threadIdx.x>>5] = v;
    __syncthreads();
    float s = 0.f;
    #pragma unroll
    for(int i=0;i<8;i++) s += sh[i];
    return s;
}

__device__ __forceinline__ uint32_t smem_u32(const void* p){
    uint32_t a;
    asm("{ .reg .u64 t; cvta.to.shared.u64 t, %1; cvt.u32.u64 %0, t; }" : "=r"(a) : "l"(p));
    return a;
}
__device__ __forceinline__ void cp16(uint32_t s, const void* g){
    asm volatile("cp.async.cg.shared.global [%0], [%1], 16;" :: "r"(s), "l"(g));
}
__device__ __forceinline__ void cp_commit(){
    asm volatile("cp.async.commit_group;" ::: "memory");
}
template<int N>
__device__ __forceinline__ void cp_wait(){
    asm volatile("cp.async.wait_group %0;" :: "n"(N) : "memory");
}
__device__ __forceinline__ void ldm_x4(uint32_t* r, uint32_t addr){
    asm volatile("ldmatrix.sync.aligned.m8n8.x4.shared.b16 {%0,%1,%2,%3}, [%4];"
        : "=r"(r[0]), "=r"(r[1]), "=r"(r[2]), "=r"(r[3]) : "r"(addr));
}
__device__ __forceinline__ void mma16816(float* d, const uint32_t* a, const uint32_t* b){
    asm volatile("mma.sync.aligned.m16n8k16.row.col.f32.f16.f16.f32 "
        "{%0,%1,%2,%3}, {%4,%5,%6,%7}, {%8,%9}, {%0,%1,%2,%3};"
        : "+f"(d[0]), "+f"(d[1]), "+f"(d[2]), "+f"(d[3])
        : "r"(a[0]), "r"(a[1]), "r"(a[2]), "r"(a[3]), "r"(b[0]), "r"(b[1]));
}

// ---------------- HMMA fp16 2-term GEMM ----------------
// C[M,N] = A[M,K]*B[N,K]^T ~fp32 via fp16 split: ah*bh + al*bh.
// CTA 128x128, BK=32, 8 warps, 3-stage cp.async, interleaved ldmatrix/MMA.
// EPI: 0 = plain fp32 store, 1 = +residual, 2 = swiglu(silu(Gl)*acc) -> mh/ml fp16
#define BM 128
#define BN 128
#define ASTR 40   // fp16 row stride in smem (80B) -> conflict-free ldmatrix
#define STG_BYTES (BM*ASTR*2)        // 10240 per matrix per stage
#define STAGE_BYTES (2*STG_BYTES)    // A + B
#define GSM_BYTES (3*STAGE_BYTES)    // 61440

template<int EPI>
__global__ void __launch_bounds__(256,2)
hm_gemm(const __half* __restrict__ Ah, const __half* __restrict__ Al,
        const __half* __restrict__ Bh,
        const float* __restrict__ Aux,       // EPI1: residual; EPI2: gl
        float* __restrict__ C,               // EPI0/1 output
        __half* __restrict__ Mh, __half* __restrict__ Ml,  // EPI2 outputs
        int K, int ldc)
{
    extern __shared__ __align__(16) char smem_raw[];

    int tid = threadIdx.x, wid = tid>>5, lane = tid&31;
    int rowBase = blockIdx.y*BM, colBase = blockIdx.x*BN;
    int wr = wid & 3, wc = wid >> 2;
    int mBase = wr*32, nBase = wc*64;

    int nk = K >> 5;          // K/32 chunks per segment
    int nIter = 2*nk;

    float acc[2][8][4];
    #pragma unroll
    for(int mi=0;mi<2;mi++)
        #pragma unroll
        for(int ni=0;ni<8;ni++)
            #pragma unroll
            for(int q=0;q<4;q++) acc[mi][ni][q]=0.f;

    // loader indices: 512 16B-chunks per matrix, 2 per thread
    int lr = tid >> 2;          // row (0..63; +64 with j)
    int lc = tid & 3;           // 16B-chunk within 32-col row

    uint32_t aS[3][2], bS[3][2];
    #pragma unroll
    for(int s=0;s<3;s++){
        #pragma unroll
        for(int j=0;j<2;j++){
            int r = lr + j*64;
            uint32_t off = (uint32_t)((r*ASTR + lc*8)*2);
            aS[s][j] = smem_u32(smem_raw + s*STAGE_BYTES + off);
            bS[s][j] = smem_u32(smem_raw + s*STAGE_BYTES + STG_BYTES + off);
        }
    }

    auto stage = [&](int it){
        if(it < nIter){
            int buf = it % 3;
            int seg = it / nk, cc = it - seg*nk;
            const __half* As = seg ? Al : Ah;
            int k0 = cc<<5;
            #pragma unroll
            for(int j=0;j<2;j++){
                int r = lr + j*64;
                cp16(aS[buf][j], As + (size_t)(rowBase+r)*K + k0 + lc*8);
                cp16(bS[buf][j], Bh + (size_t)(colBase+r)*K + k0 + lc*8);
            }
        }
        cp_commit();   // uniform group count even when empty
    };

    // prologue: stages 0,1
    stage(0);
    stage(1);

    // precompute ldmatrix smem offsets per stage
    uint32_t aL[3], bL[3];
    {
        int arow = mBase + (lane&15);
        int acol = (lane>>4)<<3;
        int brow = nBase + (lane&7) + (((lane>>4)&1)<<3);
        int bcol = ((lane>>3)&1)<<3;
        #pragma unroll
        for(int s=0;s<3;s++){
            aL[s] = smem_u32(smem_raw + s*STAGE_BYTES + (uint32_t)((arow*ASTR + acol)*2));
            bL[s] = smem_u32(smem_raw + s*STAGE_BYTES + STG_BYTES + (uint32_t)((brow*ASTR + bcol)*2));
        }
    }

    for(int it=0; it<nIter; it++){
        int buf = it % 3;
        cp_wait<1>();          // stage `it` resident
        __syncthreads();

        #pragma unroll
        for(int ks=0; ks<2; ks++){
            uint32_t af[2][4];
            #pragma unroll
            for(int mi=0;mi<2;mi++)
                ldm_x4(af[mi], aL[buf] + (uint32_t)((mi*16*ASTR + ks*16)*2));
            // interleave B fragment loads with their MMAs (LSU/tensor overlap)
            #pragma unroll
            for(int n4=0;n4<4;n4++){
                uint32_t r4[4];
                ldm_x4(r4, bL[buf] + (uint32_t)((n4*16*ASTR + ks*16)*2));
                mma16816(acc[0][n4*2+0], af[0], &r4[0]);
                mma16816(acc[0][n4*2+1], af[0], &r4[2]);
                mma16816(acc[1][n4*2+0], af[1], &r4[0]);
                mma16816(acc[1][n4*2+1], af[1], &r4[2]);
            }
        }

        stage(it+2);
    }

    // epilogue
    int qr = lane>>2, qc = lane&3;
    #pragma unroll
    for(int mi=0;mi<2;mi++){
        #pragma unroll
        for(int ni=0;ni<8;ni++){
            int row0 = rowBase + mBase + mi*16 + qr;
            int col  = colBase + nBase + ni*8 + qc*2;
            float2 v0 = make_float2(acc[mi][ni][0], acc[mi][ni][1]);
            float2 v1 = make_float2(acc[mi][ni][2], acc[mi][ni][3]);
            if(EPI==1){
                float2 r0 = *(const float2*)(Aux + (size_t)row0*ldc + col);
                float2 r1 = *(const float2*)(Aux + (size_t)(row0+8)*ldc + col);
                v0.x+=r0.x; v0.y+=r0.y; v1.x+=r1.x; v1.y+=r1.y;
            }
            if(EPI<=1){
                *(float2*)(C + (size_t)row0*ldc + col) = v0;
                *(float2*)(C + (size_t)(row0+8)*ldc + col) = v1;
            } else {
                // swiglu: m = silu(gl) * u  -> hi/lo fp16
                float2 g0 = *(const float2*)(Aux + (size_t)row0*ldc + col);
                float2 g1 = *(const float2*)(Aux + (size_t)(row0+8)*ldc + col);
                float m00 = g0.x*sigmoidf_(g0.x)*v0.x;
                float m01 = g0.y*sigmoidf_(g0.y)*v0.y;
                float m10 = g1.x*sigmoidf_(g1.x)*v1.x;
                float m11 = g1.y*sigmoidf_(g1.y)*v1.y;
                __half h00=__float2half(m00), h01=__float2half(m01);
                __half h10=__float2half(m10), h11=__float2half(m11);
                *(__half2*)(Mh + (size_t)row0*ldc + col)     = __halves2half2(h00,h01);
                *(__half2*)(Mh + (size_t)(row0+8)*ldc + col) = __halves2half2(h10,h11);
                *(__half2*)(Ml + (size_t)row0*ldc + col)     = __halves2half2(
                    __float2half(m00-__half2float(h00)), __float2half(m01-__half2float(h01)));
                *(__half2*)(Ml + (size_t)(row0+8)*ldc + col) = __halves2half2(
                    __float2half(m10-__half2float(h10)), __float2half(m11-__half2float(h11)));
            }
        }
    }
}

// ---------------- hi/lo conversion ----------------
__global__ void k_cvt2(const float* __restrict__ in, int ld, int cols,
                       __half* __restrict__ hi, __half* __restrict__ lo){
    int r = blockIdx.x;
    const float* ip = in + (size_t)r*ld;
    __half* hp = hi + (size_t)r*cols;
    __half* lp = lo + (size_t)r*cols;
    for(int c = threadIdx.x*4; c < cols; c += 1024){
        float4 v = *(const float4*)(ip + c);
        __half h0=__float2half(v.x), h1=__float2half(v.y);
        __half h2=__float2half(v.z), h3=__float2half(v.w);
        *(__half2*)(hp+c)   = __halves2half2(h0,h1);
        *(__half2*)(hp+c+2) = __halves2half2(h2,h3);
        *(__half2*)(lp+c)   = __halves2half2(
            __float2half(v.x-__half2float(h0)), __float2half(v.y-__half2float(h1)));
        *(__half2*)(lp+c+2) = __halves2half2(
            __float2half(v.z-__half2float(h2)), __float2half(v.w-__half2float(h3)));
    }
}

// weights: hi only
__global__ void k_cvtw(const float* __restrict__ in, int ld, int cols,
                       __half* __restrict__ hi){
    int r = blockIdx.x;
    const float* ip = in + (size_t)r*ld;
    __half* hp = hi + (size_t)r*cols;
    for(int c = threadIdx.x*4; c < cols; c += 1024){
        float4 v = *(const float4*)(ip + c);
        *(__half2*)(hp+c)   = __halves2half2(__float2half(v.x), __float2half(v.y));
        *(__half2*)(hp+c+2) = __halves2half2(__float2half(v.z), __float2half(v.w));
    }
}

// ---------------- small warp-dot kernels ----------------
__global__ void k_es(const float* __restrict__ prev, const float* __restrict__ W,
                     float* __restrict__ es){
    int b = blockIdx.y;
    int w = threadIdx.x>>5, l = threadIdx.x&31;
    int i = blockIdx.x*8 + w;
    const float* pr = prev + b*D_;
    const float* wr = W + (size_t)i*D_;
    float s=0.f;
    for(int j=l;j<D_;j+=32) s += pr[j]*wr[j];
    #pragma unroll
    for(int o=16;o;o>>=1) s += __shfl_xor_sync(0xffffffffu,s,o);
    if(!l) es[b*D_+i]=s;
}

__global__ void k_ge(const float* __restrict__ es, const float* __restrict__ Wg,
                     const float* __restrict__ bias, float* __restrict__ ge){
    int b = blockIdx.y;
    int w = threadIdx.x>>5, l = threadIdx.x&31;
    int i = blockIdx.x*8 + w;
    const float* er = es + b*D_;
    const float* wr = Wg + (size_t)i*(2*D_) + D_;
    float s=0.f;
    for(int j=l;j<D_;j+=32) s += er[j]*wr[j];
    #pragma unroll
    for(int o=16;o;o>>=1) s += __shfl_xor_sync(0xffffffffu,s,o);
    if(!l) ge[b*D_+i] = s + bias[i];
}

// ---------------- elementwise fusion ----------------
__global__ void k_fuse(const float* __restrict__ x, const float* __restrict__ gx,
                       const float* __restrict__ ge, const float* __restrict__ es,
                       float* __restrict__ xf){
    size_t idx = (size_t)blockIdx.x*256 + threadIdx.x;
    int i = (int)(idx & (D_-1));
    int m = (int)(idx >> 10);
    int b = m >> 11;
    float g = sigmoidf_(gx[idx] + ge[b*D_+i]);
    float e = es[b*D_+i];
    xf[idx] = g*x[idx] + (1.f-g)*e;
}

// RMSNorm over D=1024: optional fp32 out + hi/lo fp16 out
template<bool F32OUT>
__global__ void k_rms2(const float* __restrict__ in, const float* __restrict__ w,
                       float* __restrict__ out,
                       __half* __restrict__ hi, __half* __restrict__ lo){
    int row = blockIdx.x, tid = threadIdx.x;
    const float4* ir = (const float4*)(in + (size_t)row*D_);
    float4 v = ir[tid];
    float ss = blockReduce256(v.x*v.x+v.y*v.y+v.z*v.z+v.w*v.w);
    float sc = rsqrtf(ss*(1.f/D_) + EPS_);
    float4 ww = ((const float4*)w)[tid];
    float4 y = make_float4(v.x*sc*ww.x, v.y*sc*ww.y, v.z*sc*ww.z, v.w*sc*ww.w);
    if(F32OUT) ((float4*)(out + (size_t)row*D_))[tid] = y;
    int c = tid*4;
    __half* hp = hi + (size_t)row*D_;
    __half* lp = lo + (size_t)row*D_;
    __half h0=__float2half(y.x), h1=__float2half(y.y);
    __half h2=__float2half(y.z), h3=__float2half(y.w);
    *(__half2*)(hp+c)   = __halves2half2(h0,h1);
    *(__half2*)(hp+c+2) = __halves2half2(h2,h3);
    *(__half2*)(lp+c)   = __halves2half2(
        __float2half(y.x-__half2float(h0)), __float2half(y.y-__half2float(h1)));
    *(__half2*)(lp+c+2) = __halves2half2(
        __float2half(y.z-__half2float(h2)), __float2half(y.w-__half2float(h3)));
}

// beta + decay gate from h
__global__ void k_ba(const float* __restrict__ h, const float* __restrict__ bw,
                     const float* __restrict__ aw, const float* __restrict__ A_log,
                     const float* __restrict__ dtb,
                     float* __restrict__ beta, float* __restrict__ eg){
    int row = blockIdx.x;
    int b = row >> 11, t = row & (T_-1);
    int w = threadIdx.x>>5, l = threadIdx.x&31;
    const float* hr = h + (size_t)row*D_;
    {
        const float* wr = bw + (size_t)w*D_;
        float s=0.f;
        for(int j=l;j<D_;j+=32) s += hr[j]*wr[j];
        #pragma unroll
        for(int o=16;o;o>>=1) s += __shfl_xor_sync(0xffffffffu,s,o);
        if(!l){
            int i = w>>2, hh = w&3;
            beta[(( (b*NH_+i)*H_+hh )*T_) + t] = 2.f*sigmoidf_(s);
        }
    }
    if(w < H_){
        const float* ar = aw + (size_t)w*D_;
        float s=0.f;
        for(int j=l;j<D_;j+=32) s += hr[j]*ar[j];
        #pragma unroll
        for(int o=16;o;o>>=1) s += __shfl_xor_sync(0xffffffffu,s,o);
        if(!l){
            float g = -expf(A_log[w]) * softplusf_(s + dtb[w]);
            eg[(b*H_+w)*T_ + t] = expf(g);
        }
    }
}

// causal depthwise conv (K=4) + silu (+ optional L2 norm per head) + relayout
template<bool NORM>
__global__ void k_conv(const float* __restrict__ in, const float* __restrict__ cw,
                       float* __restrict__ out, int nheads){
    int t = blockIdx.x, hd = blockIdx.y, b = blockIdx.z, c = threadIdx.x;
    int C = nheads*256;
    int ch = hd*256 + c;
    const float* wp = cw + (size_t)ch*KC_;
    float acc = 0.f;
    #pragma unroll
    for(int j=0;j<KC_;j++){
        int tt = t - (KC_-1) + j;
        if(tt>=0) acc += in[((size_t)(b*T_+tt))*C + ch]*wp[j];
    }
    float s = acc * sigmoidf_(acc);
    float y;
    if(NORM){
        float ss = blockReduce256(s*s);
        y = s * rsqrtf(ss + EPS_);
    } else y = s;
    out[(((size_t)(b*nheads+hd)*T_)+t)*256 + c] = y;
}

// ---------------- gated delta-product scan ----------------
// Bank-conflict-free smem layout (SSEG=36 padded segments).
#define SSEG 36
__global__ void __launch_bounds__(256) k_scan(
    const float* __restrict__ qn, const float* __restrict__ kn,
    const float* __restrict__ vn, const float* __restrict__ beta,
    const float* __restrict__ eg, float* __restrict__ o){
    int cta = blockIdx.x;
    int ch = cta & 7;
    int hh = (cta>>3)&3;
    int b  = cta>>5;
    int vbase = ch*32;
    int tid = threadIdx.x;
    int w = tid>>5, l = tid&31;
    int col = w*4 + (l>>3);
    int kseg = l&7;

    __shared__ float sq[2][8*SSEG], sk0[2][8*SSEG], sk1[2][8*SSEG];
    __shared__ float sv0[2][32], sv1[2][32], ssc[2][4];

    int spos = (tid>>5)*SSEG + (tid&31);
    int kbase = kseg*SSEG;

    float S[32];
    #pragma unroll
    for(int j=0;j<32;j++) S[j]=0.f;

    const float* qrow  = qn + (size_t)(b*H_+hh)*T_*256;
    const float* k0row = kn + (size_t)(b*8 + hh)*T_*256;
    const float* k1row = kn + (size_t)(b*8 + H_ + hh)*T_*256;
    const float* v0row = vn + (size_t)(b*8 + hh)*T_*256 + vbase;
    const float* v1row = vn + (size_t)(b*8 + H_ + hh)*T_*256 + vbase;
    const float* b0p = beta + ((b*NH_+0)*H_+hh)*T_;
    const float* b1p = beta + ((b*NH_+1)*H_+hh)*T_;
    const float* egp = eg + (b*H_+hh)*T_;

    sq [0][spos] = qrow[tid];
    sk0[0][spos] = k0row[tid];
    sk1[0][spos] = k1row[tid];
    if(tid<32) sv0[0][tid] = v0row[tid];
    else if(tid<64) sv1[0][tid-32] = v1row[tid-32];
    if(tid==64) ssc[0][0]=b0p[0];
    if(tid==65) ssc[0][1]=b1p[0];
    if(tid==66) ssc[0][2]=egp[0];
    __syncthreads();

    const float out_scale = rsqrtf((float)DK_);

    for(int t=0;t<T_;t++){
        int cb = t&1, nb = cb^1;
        bool hn = (t+1 < T_);
        float pq=0.f, pk0=0.f, pk1=0.f, pv=0.f, psc=0.f;
        if(hn){
            size_t off = (size_t)(t+1)*256;
            pq  = qrow [off+tid];
            pk0 = k0row[off+tid];
            pk1 = k1row[off+tid];
            if(tid<32) pv = v0row[off+tid];
            else if(tid<64) pv = v1row[off + tid-32];
            if(tid==64) psc = b0p[t+1];
            if(tid==65) psc = b1p[t+1];
            if(tid==66) psc = egp[t+1];
        }

        float egv = ssc[cb][2];
        float b0v = ssc[cb][0], b1v = ssc[cb][1];
        float v0c = sv0[cb][col], v1c = sv1[cb][col];

        #pragma unroll
        for(int j=0;j<32;j++) S[j] *= egv;

        float kr[32];
        {
            const float4* kp = (const float4*)(&sk0[cb][kbase]);
            #pragma unroll
            for(int j=0;j<8;j++){ float4 k4 = kp[j];
                kr[j*4+0]=k4.x; kr[j*4+1]=k4.y; kr[j*4+2]=k4.z; kr[j*4+3]=k4.w; }
            float p0=0.f,p1=0.f,p2=0.f,p3=0.f;
            #pragma unroll
            for(int j=0;j<8;j++){
                p0 += S[j*4+0]*kr[j*4+0];
                p1 += S[j*4+1]*kr[j*4+1];
                p2 += S[j*4+2]*kr[j*4+2];
                p3 += S[j*4+3]*kr[j*4+3];
            }
            float pred = (p0+p1)+(p2+p3);
            pred += __shfl_xor_sync(0xffffffffu,pred,1);
            pred += __shfl_xor_sync(0xffffffffu,pred,2);
            pred += __shfl_xor_sync(0xffffffffu,pred,4);
            float u = (v0c - pred)*b0v;
            #pragma unroll
            for(int j=0;j<32;j++) S[j] += kr[j]*u;
        }
        {
            const float4* kp = (const float4*)(&sk1[cb][kbase]);
            #pragma unroll
            for(int j=0;j<8;j++){ float4 k4 = kp[j];
                kr[j*4+0]=k4.x; kr[j*4+1]=k4.y; kr[j*4+2]=k4.z; kr[j*4+3]=k4.w; }
            float p0=0.f,p1=0.f,p2=0.f,p3=0.f;
            #pragma unroll
            for(int j=0;j<8;j++){
                p0 += S[j*4+0]*kr[j*4+0];
                p1 += S[j*4+1]*kr[j*4+1];
                p2 += S[j*4+2]*kr[j*4+2];
                p3 += S[j*4+3]*kr[j*4+3];
            }
            float pred = (p0+p1)+(p2+p3);
            pred += __shfl_xor_sync(0xffffffffu,pred,1);
            pred += __shfl_xor_sync(0xffffffffu,pred,2);
            pred += __shfl_xor_sync(0xffffffffu,pred,4);
            float u = (v1c - pred)*b1v;
            #pragma unroll
            for(int j=0;j<32;j++) S[j] += kr[j]*u;
        }
        {
            const float4* qp = (const float4*)(&sq[cb][kbase]);
            float p0=0.f,p1=0.f;
            #pragma unroll
            for(int j=0;j<8;j++){ float4 q4 = qp[j];
                p0 += S[j*4+0]*q4.x + S[j*4+1]*q4.y;
                p1 += S[j*4+2]*q4.z + S[j*4+3]*q4.w; }
            float po = p0+p1;
            po += __shfl_xor_sync(0xffffffffu,po,1);
            po += __shfl_xor_sync(0xffffffffu,po,2);
            po += __shfl_xor_sync(0xffffffffu,po,4);
            if(kseg==0)
                o[(((size_t)(b*T_+t))*H_ + hh)*256 + vbase + col] = po*out_scale;
        }

        if(hn){
            sq [nb][spos]=pq; sk0[nb][spos]=pk0; sk1[nb][spos]=pk1;
            if(tid<32) sv0[nb][tid]=pv;
            else if(tid<64) sv1[nb][tid-32]=pv;
            if(tid==64) ssc[nb][0]=psc;
            if(tid==65) ssc[nb][1]=psc;
            if(tid==66) ssc[nb][2]=psc;
        }
        __syncthreads();
    }
}

// per-head RMSNorm over DV=256 -> hi/lo fp16
__global__ void k_onorm(const float* __restrict__ o, const float* __restrict__ w,
                        __half* __restrict__ hi, __half* __restrict__ lo){
    int row = blockIdx.x, tid = threadIdx.x;
    float v = o[(size_t)row*256 + tid];
    float ss = blockReduce256(v*v);
    float y = v * rsqrtf(ss*(1.f/256.f) + EPS_) * w[tid];
    __half h = __float2half(y);
    hi[(size_t)row*256 + tid] = h;
    lo[(size_t)row*256 + tid] = __float2half(y - __half2float(h));
}

__global__ void k_last(const float* __restrict__ out, float* __restrict__ dst){
    int idx = blockIdx.x*256 + threadIdx.x; // B*D = 8192
    int b = idx >> 10, i = idx & (D_-1);
    dst[idx] = out[((size_t)(b*T_ + (T_-1)))*D_ + i];
}

// ---------------- launcher ----------------
extern "C" void kernel_launch(void* const* d_in, const int* in_sizes, int n_in,
                              void* d_out, int out_size){
    const float* x    = (const float*)d_in[0];
    const float* prev = (const float*)d_in[1];
    const float* spw  = (const float*)d_in[2];
    const float* sgw  = (const float*)d_in[3];
    const float* sgb  = (const float*)d_in[4];
    const float* anw  = (const float*)d_in[5];
    const float* qw   = (const float*)d_in[6];
    const float* kw   = (const float*)d_in[7];
    const float* vw   = (const float*)d_in[8];
    const float* bw   = (const float*)d_in[9];
    const float* aw   = (const float*)d_in[10];
    const float* Alog = (const float*)d_in[11];
    const float* dtb  = (const float*)d_in[12];
    const float* qcw  = (const float*)d_in[13];
    const float* kcw  = (const float*)d_in[14];
    const float* vcw  = (const float*)d_in[15];
    const float* onw  = (const float*)d_in[16];
    const float* ow   = (const float*)d_in[17];
    const float* mnw  = (const float*)d_in[18];
    const float* gw   = (const float*)d_in[19];
    const float* uw   = (const float*)d_in[20];
    const float* dw   = (const float*)d_in[21];
    float* out = (float*)d_out;

    float *es,*ge,*gx,*xf,*h,*qlin,*klin,*vlin,*qn,*kn,*vn,*beta,*eg,*ob,*x2,*gl;
    cudaGetSymbolAddress((void**)&es, g_es);
    cudaGetSymbolAddress((void**)&ge, g_ge);
    cudaGetSymbolAddress((void**)&gx, g_gx);
    cudaGetSymbolAddress((void**)&xf, g_xf);
    cudaGetSymbolAddress((void**)&h,  g_h);
    cudaGetSymbolAddress((void**)&qlin, g_qlin);
    cudaGetSymbolAddress((void**)&klin, g_klin);
    cudaGetSymbolAddress((void**)&vlin, g_vlin);
    cudaGetSymbolAddress((void**)&qn, g_qn);
    cudaGetSymbolAddress((void**)&kn, g_kn);
    cudaGetSymbolAddress((void**)&vn, g_vn);
    cudaGetSymbolAddress((void**)&beta, g_beta);
    cudaGetSymbolAddress((void**)&eg, g_eg);
    cudaGetSymbolAddress((void**)&ob, g_o);
    cudaGetSymbolAddress((void**)&x2, g_x2);
    cudaGetSymbolAddress((void**)&gl, g_gl);

    __half *xh,*xl,*hh,*hl,*onh,*onl,*h2h,*h2l,*mh,*ml;
    __half *wsgh,*wqh,*wkh,*wvh,*woh,*wgh,*wuh,*wdh;
    cudaGetSymbolAddress((void**)&xh, g_xh);   cudaGetSymbolAddress((void**)&xl, g_xl);
    cudaGetSymbolAddress((void**)&hh, g_hh);   cudaGetSymbolAddress((void**)&hl, g_hl);
    cudaGetSymbolAddress((void**)&onh, g_onh); cudaGetSymbolAddress((void**)&onl, g_onl);
    cudaGetSymbolAddress((void**)&h2h, g_h2h); cudaGetSymbolAddress((void**)&h2l, g_h2l);
    cudaGetSymbolAddress((void**)&mh, g_mh);   cudaGetSymbolAddress((void**)&ml, g_ml);
    cudaGetSymbolAddress((void**)&wsgh, g_wsgh);
    cudaGetSymbolAddress((void**)&wqh, g_wqh);
    cudaGetSymbolAddress((void**)&wkh, g_wkh);
    cudaGetSymbolAddress((void**)&wvh, g_wvh);
    cudaGetSymbolAddress((void**)&woh, g_woh);
    cudaGetSymbolAddress((void**)&wgh, g_wgh);
    cudaGetSymbolAddress((void**)&wuh, g_wuh);
    cudaGetSymbolAddress((void**)&wdh, g_wdh);

    cudaFuncSetAttribute(hm_gemm<0>, cudaFuncAttributeMaxDynamicSharedMemorySize, GSM_BYTES);
    cudaFuncSetAttribute(hm_gemm<1>, cudaFuncAttributeMaxDynamicSharedMemorySize, GSM_BYTES);
    cudaFuncSetAttribute(hm_gemm<2>, cudaFuncAttributeMaxDynamicSharedMemorySize, GSM_BYTES);

    // launches 0-2; profiled ncu slot = index 3 -> keep hm_gemm there
    k_cvtw<<<1024, 256>>>(sgw, 2*D_, D_, wsgh);        // 0
    k_cvt2<<<MT_, 256>>>(x, D_, D_, xh, xl);           // 1
    k_es<<<dim3(D_/8, B_), 256>>>(prev, spw, es);      // 2

    // ---- state fusion gate GEMM (launch 3, profiled) ----
    hm_gemm<0><<<dim3(D_/BN, MT_/BM), 256, GSM_BYTES>>>(xh, xl, wsgh, nullptr, gx, nullptr, nullptr, D_, D_);

    k_ge<<<dim3(D_/8, B_), 256>>>(es, sgw, sgb, ge);
    k_fuse<<<MT_*D_/256, 256>>>(x, gx, ge, es, xf);

    // ---- remaining weight conversions ----
    k_cvtw<<<1024, 256>>>(qw, D_, D_, wqh);
    k_cvtw<<<2048, 256>>>(kw, D_, D_, wkh);
    k_cvtw<<<2048, 256>>>(vw, D_, D_, wvh);
    k_cvtw<<<1024, 256>>>(ow, D_, D_, woh);
    k_cvtw<<<I_, 256>>>(gw, D_, D_, wgh);
    k_cvtw<<<I_, 256>>>(uw, D_, D_, wuh);
    k_cvtw<<<1024, 256>>>(dw, I_, I_, wdh);

    // ---- attention sub-block ----
    k_rms2<true><<<MT_, 256>>>(xf, anw, h, hh, hl);
    hm_gemm<0><<<dim3(D_/BN, MT_/BM), 256, GSM_BYTES>>>(hh, hl, wqh, nullptr, qlin, nullptr, nullptr, D_, D_);
    hm_gemm<0><<<dim3(2048/BN, MT_/BM), 256, GSM_BYTES>>>(hh, hl, wkh, nullptr, klin, nullptr, nullptr, D_, 2048);
    hm_gemm<0><<<dim3(2048/BN, MT_/BM), 256, GSM_BYTES>>>(hh, hl, wvh, nullptr, vlin, nullptr, nullptr, D_, 2048);
    k_ba<<<MT_, 256>>>(h, bw, aw, Alog, dtb, beta, eg);
    k_conv<true ><<<dim3(T_, H_,      B_), 256>>>(qlin, qcw, qn, H_);
    k_conv<true ><<<dim3(T_, NH_*H_, B_), 256>>>(klin, kcw, kn, NH_*H_);
    k_conv<false><<<dim3(T_, NH_*H_, B_), 256>>>(vlin, vcw, vn, NH_*H_);

    k_scan<<<B_*H_*8, 256>>>(qn, kn, vn, beta, eg, ob);

    k_onorm<<<MT_*H_, 256>>>(ob, onw, onh, onl);
    hm_gemm<1><<<dim3(D_/BN, MT_/BM), 256, GSM_BYTES>>>(onh, onl, woh, xf, x2, nullptr, nullptr, D_, D_);

    // ---- MLP ----
    k_rms2<false><<<MT_, 256>>>(x2, mnw, nullptr, h2h, h2l);
    hm_gemm<0><<<dim3(I_/BN, MT_/BM), 256, GSM_BYTES>>>(h2h, h2l, wgh, nullptr, gl, nullptr, nullptr, D_, I_);
    // up-proj GEMM with fused swiglu + fp16 split epilogue (reads gl, writes mh/ml)
    hm_gemm<2><<<dim3(I_/BN, MT_/BM), 256, GSM_BYTES>>>(h2h, h2l, wuh, gl, nullptr, mh, ml, D_, I_);
    hm_gemm<1><<<dim3(D_/BN, MT_/BM), 256, GSM_BYTES>>>(mh, ml, wdh, x2, out, nullptr, nullptr, I_, D_);

    // ---- second output: final hidden state ----
    k_last<<<B_*D_/256, 256>>>(out, out + (size_t)MT_*D_);
}

// round 17
// speedup vs baseline: 1.5962x; 1.5962x over previous
#include <cuda_runtime.h>
#include <cuda_fp16.h>
#include <math.h>
#include <stdint.h>

// Problem constants
#define B_ 8
#define T_ 2048
#define D_ 1024
#define H_ 4
#define DK_ 256
#define DV_ 256
#define NH_ 2
#define KC_ 4
#define I_ 2816
#define EPS_ 1e-6f

#define MT_ (B_*T_)          // 16384 rows

// ---------------- scratch (device globals; no allocation allowed) ----------------
__device__ float g_es[B_*D_];
__device__ float g_ge[B_*D_];
__device__ float g_gx[MT_*D_];
__device__ float g_xf[MT_*D_];
__device__ float g_h [MT_*D_];
__device__ float g_qlin[MT_*D_];
__device__ float g_klin[MT_*2048];
__device__ float g_vlin[MT_*2048];
__device__ float g_qn[MT_*D_];          // [B,H,T,DK]
__device__ float g_kn[MT_*2048];        // [B,NH*H,T,DK]
__device__ float g_vn[MT_*2048];        // [B,NH*H,T,DV]
__device__ float g_beta[B_*NH_*H_*T_];
__device__ float g_eg[B_*H_*T_];
__device__ float g_o [MT_*D_];          // [B,T,H,DV]
__device__ float g_x2[MT_*D_];
__device__ float g_gl[MT_*I_];
__device__ float g_ul[MT_*I_];

// fp16 hi/lo split scratch (activations)
__device__ __half g_xh[MT_*D_],  g_xl[MT_*D_];
__device__ __half g_hh[MT_*D_],  g_hl[MT_*D_];
__device__ __half g_onh[MT_*D_], g_onl[MT_*D_];
__device__ __half g_h2h[MT_*D_], g_h2l[MT_*D_];
__device__ __half g_mh[MT_*I_],  g_ml[MT_*I_];
// fp16 weights (hi only used by GEMM)
__device__ __half g_wsgh[D_*D_];
__device__ __half g_wqh[D_*D_];
__device__ __half g_wkh[2048*D_];
__device__ __half g_wvh[2048*D_];
__device__ __half g_woh[D_*D_];
__device__ __half g_wgh[I_*D_];
__device__ __half g_wuh[I_*D_];
__device__ __half g_wdh[D_*I_];

// ---------------- helpers ----------------
__device__ __forceinline__ float sigmoidf_(float x){ return 1.f/(1.f+expf(-x)); }
__device__ __forceinline__ float softplusf_(float x){ return x>20.f? x : log1pf(expf(x)); }

__device__ __forceinline__ float blockReduce256(float v){
    __shared__ float sh[8];
    #pragma unroll
    for(int o=16;o;o>>=1) v += __shfl_xor_sync(0xffffffffu, v, o);
    if((threadIdx.x&31)==0) sh[threadIdx.x>>5] = v;
    __syncthreads();
    float s = 0.f;
    #pragma unroll
    for(int i=0;i<8;i++) s += sh[i];
    return s;
}

__device__ __forceinline__ uint32_t smem_u32(const void* p){
    uint32_t a;
    asm("{ .reg .u64 t; cvta.to.shared.u64 t, %1; cvt.u32.u64 %0, t; }" : "=r"(a) : "l"(p));
    return a;
}
__device__ __forceinline__ void cp16(uint32_t s, const void* g){
    asm volatile("cp.async.cg.shared.global [%0], [%1], 16;" :: "r"(s), "l"(g));
}
__device__ __forceinline__ void cp_commit(){
    asm volatile("cp.async.commit_group;" ::: "memory");
}
template<int N>
__device__ __forceinline__ void cp_wait(){
    asm volatile("cp.async.wait_group %0;" :: "n"(N) : "memory");
}
__device__ __forceinline__ void ldm_x4(uint32_t* r, uint32_t addr){
    asm volatile("ldmatrix.sync.aligned.m8n8.x4.shared.b16 {%0,%1,%2,%3}, [%4];"
        : "=r"(r[0]), "=r"(r[1]), "=r"(r[2]), "=r"(r[3]) : "r"(addr));
}
__device__ __forceinline__ void mma16816(float* d, const uint32_t* a, const uint32_t* b){
    asm volatile("mma.sync.aligned.m16n8k16.row.col.f32.f16.f16.f32 "
        "{%0,%1,%2,%3}, {%4,%5,%6,%7}, {%8,%9}, {%0,%1,%2,%3};"
        : "+f"(d[0]), "+f"(d[1]), "+f"(d[2]), "+f"(d[3])
        : "r"(a[0]), "r"(a[1]), "r"(a[2]), "r"(a[3]), "r"(b[0]), "r"(b[1]));
}

// ---------------- HMMA fp16 2-term GEMM (unchanged from R14 best) ----------------
#define BM 128
#define BN 128
#define ASTR 40   // fp16 row stride in smem (80B) -> conflict-free ldmatrix
#define STG_BYTES (BM*ASTR*2)        // 10240 per matrix per stage
#define STAGE_BYTES (2*STG_BYTES)    // A + B
#define GSM_BYTES (3*STAGE_BYTES)    // 61440

template<bool RES>
__global__ void __launch_bounds__(256,2)
hm_gemm(const __half* __restrict__ Ah, const __half* __restrict__ Al,
        const __half* __restrict__ Bh,
        const float* __restrict__ Res, float* __restrict__ C, int K, int ldc)
{
    extern __shared__ __align__(16) char smem_raw[];

    int tid = threadIdx.x, wid = tid>>5, lane = tid&31;
    int rowBase = blockIdx.y*BM, colBase = blockIdx.x*BN;
    int wr = wid & 3, wc = wid >> 2;
    int mBase = wr*32, nBase = wc*64;

    int nk = K >> 5;          // K/32 chunks per segment
    int nIter = 2*nk;

    float acc[2][8][4];
    #pragma unroll
    for(int mi=0;mi<2;mi++)
        #pragma unroll
        for(int ni=0;ni<8;ni++)
            #pragma unroll
            for(int q=0;q<4;q++) acc[mi][ni][q]=0.f;

    // loader indices: 512 16B-chunks per matrix, 2 per thread
    int lr = tid >> 2;          // row (0..63; +64 with j)
    int lc = tid & 3;           // 16B-chunk within 32-col row

    uint32_t aS[3][2], bS[3][2];
    #pragma unroll
    for(int s=0;s<3;s++){
        #pragma unroll
        for(int j=0;j<2;j++){
            int r = lr + j*64;
            uint32_t off = (uint32_t)((r*ASTR + lc*8)*2);
            aS[s][j] = smem_u32(smem_raw + s*STAGE_BYTES + off);
            bS[s][j] = smem_u32(smem_raw + s*STAGE_BYTES + STG_BYTES + off);
        }
    }

    auto stage = [&](int it){
        if(it < nIter){
            int buf = it % 3;
            int seg = it / nk, cc = it - seg*nk;
            const __half* As = seg ? Al : Ah;
            int k0 = cc<<5;
            #pragma unroll
            for(int j=0;j<2;j++){
                int r = lr + j*64;
                cp16(aS[buf][j], As + (size_t)(rowBase+r)*K + k0 + lc*8);
                cp16(bS[buf][j], Bh + (size_t)(colBase+r)*K + k0 + lc*8);
            }
        }
        cp_commit();   // uniform group count even when empty
    };

    // prologue: stages 0,1
    stage(0);
    stage(1);

    // precompute ldmatrix smem offsets per stage
    uint32_t aL[3], bL[3];
    {
        int arow = mBase + (lane&15);
        int acol = (lane>>4)<<3;
        int brow = nBase + (lane&7) + (((lane>>4)&1)<<3);
        int bcol = ((lane>>3)&1)<<3;
        #pragma unroll
        for(int s=0;s<3;s++){
            aL[s] = smem_u32(smem_raw + s*STAGE_BYTES + (uint32_t)((arow*ASTR + acol)*2));
            bL[s] = smem_u32(smem_raw + s*STAGE_BYTES + STG_BYTES + (uint32_t)((brow*ASTR + bcol)*2));
        }
    }

    for(int it=0; it<nIter; it++){
        int buf = it % 3;
        cp_wait<1>();          // stage `it` resident
        __syncthreads();

        #pragma unroll
        for(int ks=0; ks<2; ks++){
            uint32_t af[2][4], bfr[8][2];
            #pragma unroll
            for(int mi=0;mi<2;mi++)
                ldm_x4(af[mi], aL[buf] + (uint32_t)((mi*16*ASTR + ks*16)*2));
            #pragma unroll
            for(int n4=0;n4<4;n4++){
                uint32_t r4[4];
                ldm_x4(r4, bL[buf] + (uint32_t)((n4*16*ASTR + ks*16)*2));
                bfr[n4*2+0][0]=r4[0]; bfr[n4*2+0][1]=r4[1];
                bfr[n4*2+1][0]=r4[2]; bfr[n4*2+1][1]=r4[3];
            }
            #pragma unroll
            for(int mi=0;mi<2;mi++)
                #pragma unroll
                for(int ni=0;ni<8;ni++)
                    mma16816(acc[mi][ni], af[mi], bfr[ni]);
        }

        stage(it+2);
    }

    // epilogue
    int qr = lane>>2, qc = lane&3;
    #pragma unroll
    for(int mi=0;mi<2;mi++){
        #pragma unroll
        for(int ni=0;ni<8;ni++){
            int row0 = rowBase + mBase + mi*16 + qr;
            int col  = colBase + nBase + ni*8 + qc*2;
            float2 v0 = make_float2(acc[mi][ni][0], acc[mi][ni][1]);
            float2 v1 = make_float2(acc[mi][ni][2], acc[mi][ni][3]);
            if(RES){
                float2 r0 = *(const float2*)(Res + (size_t)row0*ldc + col);
                float2 r1 = *(const float2*)(Res + (size_t)(row0+8)*ldc + col);
                v0.x+=r0.x; v0.y+=r0.y; v1.x+=r1.x; v1.y+=r1.y;
            }
            *(float2*)(C + (size_t)row0*ldc + col) = v0;
            *(float2*)(C + (size_t)(row0+8)*ldc + col) = v1;
        }
    }
}

// ---------------- hi/lo conversion ----------------
__global__ void k_cvt2(const float* __restrict__ in, int ld, int cols,
                       __half* __restrict__ hi, __half* __restrict__ lo){
    int r = blockIdx.x;
    const float* ip = in + (size_t)r*ld;
    __half* hp = hi + (size_t)r*cols;
    __half* lp = lo + (size_t)r*cols;
    for(int c = threadIdx.x*4; c < cols; c += 1024){
        float4 v = *(const float4*)(ip + c);
        __half h0=__float2half(v.x), h1=__float2half(v.y);
        __half h2=__float2half(v.z), h3=__float2half(v.w);
        *(__half2*)(hp+c)   = __halves2half2(h0,h1);
        *(__half2*)(hp+c+2) = __halves2half2(h2,h3);
        *(__half2*)(lp+c)   = __halves2half2(
            __float2half(v.x-__half2float(h0)), __float2half(v.y-__half2float(h1)));
        *(__half2*)(lp+c+2) = __halves2half2(
            __float2half(v.z-__half2float(h2)), __float2half(v.w-__half2float(h3)));
    }
}

// weights: hi only
__global__ void k_cvtw(const float* __restrict__ in, int ld, int cols,
                       __half* __restrict__ hi){
    int r = blockIdx.x;
    const float* ip = in + (size_t)r*ld;
    __half* hp = hi + (size_t)r*cols;
    for(int c = threadIdx.x*4; c < cols; c += 1024){
        float4 v = *(const float4*)(ip + c);
        *(__half2*)(hp+c)   = __halves2half2(__float2half(v.x), __float2half(v.y));
        *(__half2*)(hp+c+2) = __halves2half2(__float2half(v.z), __float2half(v.w));
    }
}

// ---------------- small warp-dot kernels ----------------
__global__ void k_es(const float* __restrict__ prev, const float* __restrict__ W,
                     float* __restrict__ es){
    int b = blockIdx.y;
    int w = threadIdx.x>>5, l = threadIdx.x&31;
    int i = blockIdx.x*8 + w;
    const float* pr = prev + b*D_;
    const float* wr = W + (size_t)i*D_;
    float s=0.f;
    for(int j=l;j<D_;j+=32) s += pr[j]*wr[j];
    #pragma unroll
    for(int o=16;o;o>>=1) s += __shfl_xor_sync(0xffffffffu,s,o);
    if(!l) es[b*D_+i]=s;
}

__global__ void k_ge(const float* __restrict__ es, const float* __restrict__ Wg,
                     const float* __restrict__ bias, float* __restrict__ ge){
    int b = blockIdx.y;
    int w = threadIdx.x>>5, l = threadIdx.x&31;
    int i = blockIdx.x*8 + w;
    const float* er = es + b*D_;
    const float* wr = Wg + (size_t)i*(2*D_) + D_;
    float s=0.f;
    for(int j=l;j<D_;j+=32) s += er[j]*wr[j];
    #pragma unroll
    for(int o=16;o;o>>=1) s += __shfl_xor_sync(0xffffffffu,s,o);
    if(!l) ge[b*D_+i] = s + bias[i];
}

// ---------------- elementwise fusion ----------------
__global__ void k_fuse(const float* __restrict__ x, const float* __restrict__ gx,
                       const float* __restrict__ ge, const float* __restrict__ es,
                       float* __restrict__ xf){
    size_t idx = (size_t)blockIdx.x*256 + threadIdx.x;
    int i = (int)(idx & (D_-1));
    int m = (int)(idx >> 10);
    int b = m >> 11;
    float g = sigmoidf_(gx[idx] + ge[b*D_+i]);
    float e = es[b*D_+i];
    xf[idx] = g*x[idx] + (1.f-g)*e;
}

// RMSNorm over D=1024: optional fp32 out + hi/lo fp16 out
template<bool F32OUT>
__global__ void k_rms2(const float* __restrict__ in, const float* __restrict__ w,
                       float* __restrict__ out,
                       __half* __restrict__ hi, __half* __restrict__ lo){
    int row = blockIdx.x, tid = threadIdx.x;
    const float4* ir = (const float4*)(in + (size_t)row*D_);
    float4 v = ir[tid];
    float ss = blockReduce256(v.x*v.x+v.y*v.y+v.z*v.z+v.w*v.w);
    float sc = rsqrtf(ss*(1.f/D_) + EPS_);
    float4 ww = ((const float4*)w)[tid];
    float4 y = make_float4(v.x*sc*ww.x, v.y*sc*ww.y, v.z*sc*ww.z, v.w*sc*ww.w);
    if(F32OUT) ((float4*)(out + (size_t)row*D_))[tid] = y;
    int c = tid*4;
    __half* hp = hi + (size_t)row*D_;
    __half* lp = lo + (size_t)row*D_;
    __half h0=__float2half(y.x), h1=__float2half(y.y);
    __half h2=__float2half(y.z), h3=__float2half(y.w);
    *(__half2*)(hp+c)   = __halves2half2(h0,h1);
    *(__half2*)(hp+c+2) = __halves2half2(h2,h3);
    *(__half2*)(lp+c)   = __halves2half2(
        __float2half(y.x-__half2float(h0)), __float2half(y.y-__half2float(h1)));
    *(__half2*)(lp+c+2) = __halves2half2(
        __float2half(y.z-__half2float(h2)), __float2half(y.w-__half2float(h3)));
}

// beta + decay gate from h
__global__ void k_ba(const float* __restrict__ h, const float* __restrict__ bw,
                     const float* __restrict__ aw, const float* __restrict__ A_log,
                     const float* __restrict__ dtb,
                     float* __restrict__ beta, float* __restrict__ eg){
    int row = blockIdx.x;
    int b = row >> 11, t = row & (T_-1);
    int w = threadIdx.x>>5, l = threadIdx.x&31;
    const float* hr = h + (size_t)row*D_;
    {
        const float* wr = bw + (size_t)w*D_;
        float s=0.f;
        for(int j=l;j<D_;j+=32) s += hr[j]*wr[j];
        #pragma unroll
        for(int o=16;o;o>>=1) s += __shfl_xor_sync(0xffffffffu,s,o);
        if(!l){
            int i = w>>2, hh = w&3;
            beta[(( (b*NH_+i)*H_+hh )*T_) + t] = 2.f*sigmoidf_(s);
        }
    }
    if(w < H_){
        const float* ar = aw + (size_t)w*D_;
        float s=0.f;
        for(int j=l;j<D_;j+=32) s += hr[j]*ar[j];
        #pragma unroll
        for(int o=16;o;o>>=1) s += __shfl_xor_sync(0xffffffffu,s,o);
        if(!l){
            float g = -expf(A_log[w]) * softplusf_(s + dtb[w]);
            eg[(b*H_+w)*T_ + t] = expf(g);
        }
    }
}

// causal depthwise conv (K=4) + silu (+ optional L2 norm per head) + relayout
template<bool NORM>
__global__ void k_conv(const float* __restrict__ in, const float* __restrict__ cw,
                       float* __restrict__ out, int nheads){
    int t = blockIdx.x, hd = blockIdx.y, b = blockIdx.z, c = threadIdx.x;
    int C = nheads*256;
    int ch = hd*256 + c;
    const float* wp = cw + (size_t)ch*KC_;
    float acc = 0.f;
    #pragma unroll
    for(int j=0;j<KC_;j++){
        int tt = t - (KC_-1) + j;
        if(tt>=0) acc += in[((size_t)(b*T_+tt))*C + ch]*wp[j];
    }
    float s = acc * sigmoidf_(acc);
    float y;
    if(NORM){
        float ss = blockReduce256(s*s);
        y = s * rsqrtf(ss + EPS_);
    } else y = s;
    out[(((size_t)(b*nheads+hd)*T_)+t)*256 + c] = y;
}

// ---------------- gated delta-product scan ----------------
// 512 CTAs x 128 threads: each CTA owns 16 V-cols of one (b,h); per-thread
// layout unchanged (1 col x 32 k). SSEG=36 conflict-free smem layout.
#define SSEG 36
__global__ void __launch_bounds__(128) k_scan(
    const float* __restrict__ qn, const float* __restrict__ kn,
    const float* __restrict__ vn, const float* __restrict__ beta,
    const float* __restrict__ eg, float* __restrict__ o){
    int cta = blockIdx.x;
    int ch = cta & 15;          // 16 chunks of 16 cols
    int hh = (cta>>4)&3;
    int b  = cta>>6;
    int vbase = ch*16;
    int tid = threadIdx.x;      // 0..127
    int w = tid>>5, l = tid&31; // w 0..3
    int col = w*4 + (l>>3);     // 0..15
    int kseg = l&7;

    __shared__ float sq[2][8*SSEG], sk0[2][8*SSEG], sk1[2][8*SSEG];
    __shared__ float sv0[2][16], sv1[2][16], ssc[2][4];

    // each thread stages elements tid and tid+128 of the 256-wide k rows
    int spos0 = (tid>>5)*SSEG + (tid&31);
    int spos1 = ((tid>>5)+4)*SSEG + (tid&31);
    int kbase = kseg*SSEG;

    float S[32];
    #pragma unroll
    for(int j=0;j<32;j++) S[j]=0.f;

    const float* qrow  = qn + (size_t)(b*H_+hh)*T_*256;
    const float* k0row = kn + (size_t)(b*8 + hh)*T_*256;
    const float* k1row = kn + (size_t)(b*8 + H_ + hh)*T_*256;
    const float* v0row = vn + (size_t)(b*8 + hh)*T_*256 + vbase;
    const float* v1row = vn + (size_t)(b*8 + H_ + hh)*T_*256 + vbase;
    const float* b0p = beta + ((b*NH_+0)*H_+hh)*T_;
    const float* b1p = beta + ((b*NH_+1)*H_+hh)*T_;
    const float* egp = eg + (b*H_+hh)*T_;

    sq [0][spos0] = qrow[tid];     sq [0][spos1] = qrow[tid+128];
    sk0[0][spos0] = k0row[tid];    sk0[0][spos1] = k0row[tid+128];
    sk1[0][spos0] = k1row[tid];    sk1[0][spos1] = k1row[tid+128];
    if(tid<16) sv0[0][tid] = v0row[tid];
    else if(tid<32) sv1[0][tid-16] = v1row[tid-16];
    if(tid==32) ssc[0][0]=b0p[0];
    if(tid==33) ssc[0][1]=b1p[0];
    if(tid==34) ssc[0][2]=egp[0];
    __syncthreads();

    const float out_scale = rsqrtf((float)DK_);

    for(int t=0;t<T_;t++){
        int cb = t&1, nb = cb^1;
        bool hn = (t+1 < T_);
        float pq0=0.f,pq1=0.f, pk00=0.f,pk01=0.f, pk10=0.f,pk11=0.f, pv=0.f, psc=0.f;
        if(hn){
            size_t off = (size_t)(t+1)*256;
            pq0  = qrow [off+tid];   pq1  = qrow [off+tid+128];
            pk00 = k0row[off+tid];   pk01 = k0row[off+tid+128];
            pk10 = k1row[off+tid];   pk11 = k1row[off+tid+128];
            if(tid<16) pv = v0row[off+tid];
            else if(tid<32) pv = v1row[off + tid-16];
            if(tid==32) psc = b0p[t+1];
            if(tid==33) psc = b1p[t+1];
            if(tid==34) psc = egp[t+1];
        }

        float egv = ssc[cb][2];
        float b0v = ssc[cb][0], b1v = ssc[cb][1];
        float v0c = sv0[cb][col], v1c = sv1[cb][col];

        #pragma unroll
        for(int j=0;j<32;j++) S[j] *= egv;

        float kr[32];
        {
            const float4* kp = (const float4*)(&sk0[cb][kbase]);
            #pragma unroll
            for(int j=0;j<8;j++){ float4 k4 = kp[j];
                kr[j*4+0]=k4.x; kr[j*4+1]=k4.y; kr[j*4+2]=k4.z; kr[j*4+3]=k4.w; }
            float p0=0.f,p1=0.f,p2=0.f,p3=0.f;
            #pragma unroll
            for(int j=0;j<8;j++){
                p0 += S[j*4+0]*kr[j*4+0];
                p1 += S[j*4+1]*kr[j*4+1];
                p2 += S[j*4+2]*kr[j*4+2];
                p3 += S[j*4+3]*kr[j*4+3];
            }
            float pred = (p0+p1)+(p2+p3);
            pred += __shfl_xor_sync(0xffffffffu,pred,1);
            pred += __shfl_xor_sync(0xffffffffu,pred,2);
            pred += __shfl_xor_sync(0xffffffffu,pred,4);
            float u = (v0c - pred)*b0v;
            #pragma unroll
            for(int j=0;j<32;j++) S[j] += kr[j]*u;
        }
        {
            const float4* kp = (const float4*)(&sk1[cb][kbase]);
            #pragma unroll
            for(int j=0;j<8;j++){ float4 k4 = kp[j];
                kr[j*4+0]=k4.x; kr[j*4+1]=k4.y; kr[j*4+2]=k4.z; kr[j*4+3]=k4.w; }
            float p0=0.f,p1=0.f,p2=0.f,p3=0.f;
            #pragma unroll
            for(int j=0;j<8;j++){
                p0 += S[j*4+0]*kr[j*4+0];
                p1 += S[j*4+1]*kr[j*4+1];
                p2 += S[j*4+2]*kr[j*4+2];
                p3 += S[j*4+3]*kr[j*4+3];
            }
            float pred = (p0+p1)+(p2+p3);
            pred += __shfl_xor_sync(0xffffffffu,pred,1);
            pred += __shfl_xor_sync(0xffffffffu,pred,2);
            pred += __shfl_xor_sync(0xffffffffu,pred,4);
            float u = (v1c - pred)*b1v;
            #pragma unroll
            for(int j=0;j<32;j++) S[j] += kr[j]*u;
        }
        {
            const float4* qp = (const float4*)(&sq[cb][kbase]);
            float p0=0.f,p1=0.f;
            #pragma unroll
            for(int j=0;j<8;j++){ float4 q4 = qp[j];
                p0 += S[j*4+0]*q4.x + S[j*4+1]*q4.y;
                p1 += S[j*4+2]*q4.z + S[j*4+3]*q4.w; }
            float po = p0+p1;
            po += __shfl_xor_sync(0xffffffffu,po,1);
            po += __shfl_xor_sync(0xffffffffu,po,2);
            po += __shfl_xor_sync(0xffffffffu,po,4);
            if(kseg==0)
                o[(((size_t)(b*T_+t))*H_ + hh)*256 + vbase + col] = po*out_scale;
        }

        if(hn){
            sq [nb][spos0]=pq0;  sq [nb][spos1]=pq1;
            sk0[nb][spos0]=pk00; sk0[nb][spos1]=pk01;
            sk1[nb][spos0]=pk10; sk1[nb][spos1]=pk11;
            if(tid<16) sv0[nb][tid]=pv;
            else if(tid<32) sv1[nb][tid-16]=pv;
            if(tid==32) ssc[nb][0]=psc;
            if(tid==33) ssc[nb][1]=psc;
            if(tid==34) ssc[nb][2]=psc;
        }
        __syncthreads();
    }
}

// per-head RMSNorm over DV=256 -> hi/lo fp16
__global__ void k_onorm(const float* __restrict__ o, const float* __restrict__ w,
                        __half* __restrict__ hi, __half* __restrict__ lo){
    int row = blockIdx.x, tid = threadIdx.x;
    float v = o[(size_t)row*256 + tid];
    float ss = blockReduce256(v*v);
    float y = v * rsqrtf(ss*(1.f/256.f) + EPS_) * w[tid];
    __half h = __float2half(y);
    hi[(size_t)row*256 + tid] = h;
    lo[(size_t)row*256 + tid] = __float2half(y - __half2float(h));
}

__global__ void k_swiglu_cvt(const float* __restrict__ gl, const float* __restrict__ ul,
                             __half* __restrict__ mh, __half* __restrict__ ml,
                             size_t n4){
    size_t i4 = (size_t)blockIdx.x*256 + threadIdx.x;
    if(i4 < n4){
        size_t c = i4*4;
        float4 g4 = *(const float4*)(gl + c);
        float4 u4 = *(const float4*)(ul + c);
        float m0 = g4.x*sigmoidf_(g4.x)*u4.x;
        float m1 = g4.y*sigmoidf_(g4.y)*u4.y;
        float m2 = g4.z*sigmoidf_(g4.z)*u4.z;
        float m3 = g4.w*sigmoidf_(g4.w)*u4.w;
        __half h0=__float2half(m0), h1=__float2half(m1);
        __half h2=__float2half(m2), h3=__float2half(m3);
        *(__half2*)(mh+c)   = __halves2half2(h0,h1);
        *(__half2*)(mh+c+2) = __halves2half2(h2,h3);
        *(__half2*)(ml+c)   = __halves2half2(
            __float2half(m0-__half2float(h0)), __float2half(m1-__half2float(h1)));
        *(__half2*)(ml+c+2) = __halves2half2(
            __float2half(m2-__half2float(h2)), __float2half(m3-__half2float(h3)));
    }
}

__global__ void k_last(const float* __restrict__ out, float* __restrict__ dst){
    int idx = blockIdx.x*256 + threadIdx.x; // B*D = 8192
    int b = idx >> 10, i = idx & (D_-1);
    dst[idx] = out[((size_t)(b*T_ + (T_-1)))*D_ + i];
}

// ---------------- launcher ----------------
extern "C" void kernel_launch(void* const* d_in, const int* in_sizes, int n_in,
                              void* d_out, int out_size){
    const float* x    = (const float*)d_in[0];
    const float* prev = (const float*)d_in[1];
    const float* spw  = (const float*)d_in[2];
    const float* sgw  = (const float*)d_in[3];
    const float* sgb  = (const float*)d_in[4];
    const float* anw  = (const float*)d_in[5];
    const float* qw   = (const float*)d_in[6];
    const float* kw   = (const float*)d_in[7];
    const float* vw   = (const float*)d_in[8];
    const float* bw   = (const float*)d_in[9];
    const float* aw   = (const float*)d_in[10];
    const float* Alog = (const float*)d_in[11];
    const float* dtb  = (const float*)d_in[12];
    const float* qcw  = (const float*)d_in[13];
    const float* kcw  = (const float*)d_in[14];
    const float* vcw  = (const float*)d_in[15];
    const float* onw  = (const float*)d_in[16];
    const float* ow   = (const float*)d_in[17];
    const float* mnw  = (const float*)d_in[18];
    const float* gw   = (const float*)d_in[19];
    const float* uw   = (const float*)d_in[20];
    const float* dw   = (const float*)d_in[21];
    float* out = (float*)d_out;

    float *es,*ge,*gx,*xf,*h,*qlin,*klin,*vlin,*qn,*kn,*vn,*beta,*eg,*ob,*x2,*gl,*ul;
    cudaGetSymbolAddress((void**)&es, g_es);
    cudaGetSymbolAddress((void**)&ge, g_ge);
    cudaGetSymbolAddress((void**)&gx, g_gx);
    cudaGetSymbolAddress((void**)&xf, g_xf);
    cudaGetSymbolAddress((void**)&h,  g_h);
    cudaGetSymbolAddress((void**)&qlin, g_qlin);
    cudaGetSymbolAddress((void**)&klin, g_klin);
    cudaGetSymbolAddress((void**)&vlin, g_vlin);
    cudaGetSymbolAddress((void**)&qn, g_qn);
    cudaGetSymbolAddress((void**)&kn, g_kn);
    cudaGetSymbolAddress((void**)&vn, g_vn);
    cudaGetSymbolAddress((void**)&beta, g_beta);
    cudaGetSymbolAddress((void**)&eg, g_eg);
    cudaGetSymbolAddress((void**)&ob, g_o);
    cudaGetSymbolAddress((void**)&x2, g_x2);
    cudaGetSymbolAddress((void**)&gl, g_gl);
    cudaGetSymbolAddress((void**)&ul, g_ul);

    __half *xh,*xl,*hh,*hl,*onh,*onl,*h2h,*h2l,*mh,*ml;
    __half *wsgh,*wqh,*wkh,*wvh,*woh,*wgh,*wuh,*wdh;
    cudaGetSymbolAddress((void**)&xh, g_xh);   cudaGetSymbolAddress((void**)&xl, g_xl);
    cudaGetSymbolAddress((void**)&hh, g_hh);   cudaGetSymbolAddress((void**)&hl, g_hl);
    cudaGetSymbolAddress((void**)&onh, g_onh); cudaGetSymbolAddress((void**)&onl, g_onl);
    cudaGetSymbolAddress((void**)&h2h, g_h2h); cudaGetSymbolAddress((void**)&h2l, g_h2l);
    cudaGetSymbolAddress((void**)&mh, g_mh);   cudaGetSymbolAddress((void**)&ml, g_ml);
    cudaGetSymbolAddress((void**)&wsgh, g_wsgh);
    cudaGetSymbolAddress((void**)&wqh, g_wqh);
    cudaGetSymbolAddress((void**)&wkh, g_wkh);
    cudaGetSymbolAddress((void**)&wvh, g_wvh);
    cudaGetSymbolAddress((void**)&woh, g_woh);
    cudaGetSymbolAddress((void**)&wgh, g_wgh);
    cudaGetSymbolAddress((void**)&wuh, g_wuh);
    cudaGetSymbolAddress((void**)&wdh, g_wdh);

    cudaFuncSetAttribute(hm_gemm<false>, cudaFuncAttributeMaxDynamicSharedMemorySize, GSM_BYTES);
    cudaFuncSetAttribute(hm_gemm<true>,  cudaFuncAttributeMaxDynamicSharedMemorySize, GSM_BYTES);

    // launches 0-2; captured ncu slot = index 3 -> keep hm_gemm there
    k_cvtw<<<1024, 256>>>(sgw, 2*D_, D_, wsgh);        // 0
    k_cvt2<<<MT_, 256>>>(x, D_, D_, xh, xl);           // 1
    k_es<<<dim3(D_/8, B_), 256>>>(prev, spw, es);      // 2

    // ---- state fusion gate GEMM (launch 3, profiled) ----
    hm_gemm<false><<<dim3(D_/BN, MT_/BM), 256, GSM_BYTES>>>(xh, xl, wsgh, nullptr, gx, D_, D_);

    k_ge<<<dim3(D_/8, B_), 256>>>(es, sgw, sgb, ge);
    k_fuse<<<MT_*D_/256, 256>>>(x, gx, ge, es, xf);

    // ---- remaining weight conversions ----
    k_cvtw<<<1024, 256>>>(qw, D_, D_, wqh);
    k_cvtw<<<2048, 256>>>(kw, D_, D_, wkh);
    k_cvtw<<<2048, 256>>>(vw, D_, D_, wvh);
    k_cvtw<<<1024, 256>>>(ow, D_, D_, woh);
    k_cvtw<<<I_, 256>>>(gw, D_, D_, wgh);
    k_cvtw<<<I_, 256>>>(uw, D_, D_, wuh);
    k_cvtw<<<1024, 256>>>(dw, I_, I_, wdh);

    // ---- attention sub-block ----
    k_rms2<true><<<MT_, 256>>>(xf, anw, h, hh, hl);
    hm_gemm<false><<<dim3(D_/BN, MT_/BM), 256, GSM_BYTES>>>(hh, hl, wqh, nullptr, qlin, D_, D_);
    hm_gemm<false><<<dim3(2048/BN, MT_/BM), 256, GSM_BYTES>>>(hh, hl, wkh, nullptr, klin, D_, 2048);
    hm_gemm<false><<<dim3(2048/BN, MT_/BM), 256, GSM_BYTES>>>(hh, hl, wvh, nullptr, vlin, D_, 2048);
    k_ba<<<MT_, 256>>>(h, bw, aw, Alog, dtb, beta, eg);
    k_conv<true ><<<dim3(T_, H_,      B_), 256>>>(qlin, qcw, qn, H_);
    k_conv<true ><<<dim3(T_, NH_*H_, B_), 256>>>(klin, kcw, kn, NH_*H_);
    k_conv<false><<<dim3(T_, NH_*H_, B_), 256>>>(vlin, vcw, vn, NH_*H_);

    k_scan<<<B_*H_*16, 128>>>(qn, kn, vn, beta, eg, ob);

    k_onorm<<<MT_*H_, 256>>>(ob, onw, onh, onl);
    hm_gemm<true><<<dim3(D_/BN, MT_/BM), 256, GSM_BYTES>>>(onh, onl, woh, xf, x2, D_, D_);

    // ---- MLP ----
    k_rms2<false><<<MT_, 256>>>(x2, mnw, nullptr, h2h, h2l);
    hm_gemm<false><<<dim3(I_/BN, MT_/BM), 256, GSM_BYTES>>>(h2h, h2l, wgh, nullptr, gl, D_, I_);
    hm_gemm<false><<<dim3(I_/BN, MT_/BM), 256, GSM_BYTES>>>(h2h, h2l, wuh, nullptr, ul, D_, I_);
    {
        size_t n4 = (size_t)MT_*I_/4;
        k_swiglu_cvt<<<(unsigned)((n4+255)/256), 256>>>(gl, ul, mh, ml, n4);
    }
    hm_gemm<true><<<dim3(D_/BN, MT_/BM), 256, GSM_BYTES>>>(mh, ml, wdh, x2, out, I_, D_);

    // ---- second output: final hidden state ----
    k_last<<<B_*D_/256, 256>>>(out, out + (size_t)MT_*D_);
}